// round 17
// baseline (speedup 1.0000x reference)
#include <cuda_runtime.h>

// EMD via entropic Sinkhorn, B=16, N=2048, D=3, eps=0.05.
// Never materialize C; recompute distances from coordinates.
// R4-R14: ITERS 100->10 with theta=1.6 overrelaxation; theta/ITERS closed.
//   Cross-launch shift precompute via epilogue atomicMax. R15/R16: grid
//   balance attempts netted zero -> balance axis closed; R14 structure kept.
// R17: packed-f32x2 + hybrid exp. SoA column staging so ld.shared.b64 gives
//   packed column pairs; dots via fma.rn.f32x2 (fma pipe 32->20 cyc/unit).
//   1-in-4 column pairs evaluate exp2 via magic-constant range reduction +
//   deg-3 poly (fma pipe) + integer exponent add (alu pipe), the rest stay
//   on MUFU EX2. Per-8-col body: fma ~100 cyc, MUFU 96 (vs 128/128 before).

#define BB 16
#define NN 2048
#define ITERS 10
#define NLAUNCH (2 * ITERS)
#define RT 64              // rows per block (2 per thread)
#define GRIDX (NN / RT)    // 32

typedef unsigned long long ull;

// r = log2(e)/eps
__device__ __constant__ float kRE        = 28.85390081777927f;
// eps * ln(2)
__device__ __constant__ float kEPS_LN2   = 0.03465735902799727f;
// eps * log_mu = -eps * ln(N)
__device__ __constant__ float kEPS_LOGMU = -0.38123094930796994f;
// overrelaxation factor (empirical nonlinear optimum; 1.68 diverges)
__device__ __constant__ float kTHETA     = 1.6f;

__device__ float    d_f[BB * NN];
__device__ float    d_g[BB * NN];
__device__ float4   d_sx[BB * NN];   // {2r*x0, 2r*x1, 2r*x2, r*|x|^2}
__device__ float4   d_sy[BB * NN];   // {2r*y0, 2r*y1, 2r*y2, r*|y|^2}
__device__ float    d_part[GRIDX * BB];
__device__ unsigned d_gmax[NLAUNCH + 2][BB];  // order-encoded max dual per launch

__device__ __forceinline__ float ex2(float t) {
    float r;
    asm("ex2.approx.ftz.f32 %0, %1;" : "=f"(r) : "f"(t));
    return r;
}

// ---- packed f32x2 helpers -------------------------------------------------
__device__ __forceinline__ ull fma2(ull a, ull b, ull c) {
    ull d;
    asm("fma.rn.f32x2 %0, %1, %2, %3;" : "=l"(d) : "l"(a), "l"(b), "l"(c));
    return d;
}
__device__ __forceinline__ ull add2(ull a, ull b) {
    ull d;
    asm("add.rn.f32x2 %0, %1, %2;" : "=l"(d) : "l"(a), "l"(b));
    return d;
}
__device__ __forceinline__ ull pack2(float lo, float hi) {
    ull d;
    asm("mov.b64 %0, {%1, %2};" : "=l"(d) : "f"(lo), "f"(hi));
    return d;
}
__device__ __forceinline__ void unpack2f(ull a, float& x, float& y) {
    asm("mov.b64 {%0, %1}, %2;" : "=f"(x), "=f"(y) : "l"(a));
}

// packed exp2 via magic-constant range reduction + deg-3 poly + exponent add.
// valid for |t| < 2^21 and t > -120 (here t in [-87, 87]).
__device__ __forceinline__ ull pexp2(ull t2, ull M2, ull NM2, ull N1_2,
                                     ull C3_2, ull C2_2, ull C1_2, ull C0_2) {
    ull z2 = add2(t2, M2);          // bits hold 0x4B400000 + round(t)
    ull n2 = add2(z2, NM2);         // round(t) as float
    ull f2 = fma2(n2, N1_2, t2);    // f = t - n in [-0.5, 0.5]
    ull p2 = fma2(f2, C3_2, C2_2);
    p2 = fma2(p2, f2, C1_2);
    p2 = fma2(p2, f2, C0_2);        // ~2^f
    unsigned zl, zh, pl, ph;
    asm("mov.b64 {%0, %1}, %2;" : "=r"(zl), "=r"(zh) : "l"(z2));
    asm("mov.b64 {%0, %1}, %2;" : "=r"(pl), "=r"(ph) : "l"(p2));
    unsigned rl = pl + (zl << 23);  // scale by 2^n via exponent field
    unsigned rh = ph + (zh << 23);
    ull e2;
    asm("mov.b64 %0, {%1, %2};" : "=l"(e2) : "r"(rl), "r"(rh));
    return e2;
}

// order-preserving uint encoding of float (monotone for all finite values)
__device__ __forceinline__ unsigned fenc(float v) {
    unsigned b = __float_as_uint(v);
    return (b & 0x80000000u) ? ~b : (b | 0x80000000u);
}
__device__ __forceinline__ float fdec(unsigned u) {
    unsigned b = (u & 0x80000000u) ? (u & 0x7fffffffu) : ~u;
    return __uint_as_float(b);
}

// ---------------------------------------------------------------------------
__global__ void prep_kernel(const float* __restrict__ x,
                            const float* __restrict__ y) {
    int i = blockIdx.x * blockDim.x + threadIdx.x;
    if (i < (NLAUNCH + 2) * BB) {
        ((unsigned*)d_gmax)[i] = (i < BB) ? fenc(0.f) : fenc(-1e30f);
    }
    if (i >= BB * NN) return;
    const float r = kRE;
    float a0 = x[3 * i], a1 = x[3 * i + 1], a2 = x[3 * i + 2];
    d_sx[i] = make_float4(2.f * r * a0, 2.f * r * a1, 2.f * r * a2,
                          r * (a0 * a0 + a1 * a1 + a2 * a2));
    float b0 = y[3 * i], b1 = y[3 * i + 1], b2 = y[3 * i + 2];
    d_sy[i] = make_float4(2.f * r * b0, 2.f * r * b1, 2.f * r * b2,
                          r * (b0 * b0 + b1 * b1 + b2 * b2));
    d_g[i] = 0.f;
    d_f[i] = 0.f;
}

// ---------------------------------------------------------------------------
// One Sinkhorn half-iteration (launch index t), with overrelaxation.
// dir == 0 : rows = x, cols = y, col dual = g, writes f
// dir == 1 : rows = y, cols = x, col dual = f, writes g
// Block: 256 threads = 8 warps. Warp w handles column group [w*256, +256)
// for 64 rows; lane l owns rows l and l+32. Grid (32, 16) = 512 blocks.
// SoA smem staging; 3-of-4 column pairs via MUFU EX2, 1-of-4 via poly.
// ---------------------------------------------------------------------------
__global__ void __launch_bounds__(256, 4)
sink_update(const float* __restrict__ rowP, int dir, int t) {
    __shared__ __align__(16) float s_x[NN];
    __shared__ __align__(16) float s_y[NN];
    __shared__ __align__(16) float s_z[NN];
    __shared__ __align__(16) float s_w[NN];
    __shared__ float spart[512];

    const int b   = blockIdx.y;
    const int tid = threadIdx.x;
    const float  r    = kRE;
    const float* dual = (dir == 0 ? d_g : d_f) + b * NN;
    const float4* cs  = (dir == 0 ? d_sy : d_sx) + b * NN;
    float*       outd = (dir == 0 ? d_f : d_g) + b * NN;

    // shift S = r * max_j dual_j, precomputed by previous launch's epilogue
    const float S = r * fdec(d_gmax[t][b]);

    // SoA staging: w_j = r*dual_j - r*|p_j|^2 - S
#pragma unroll
    for (int k = 0; k < 8; k++) {
        int j = k * 256 + tid;
        float4 p = cs[j];
        s_x[j] = p.x;
        s_y[j] = p.y;
        s_z[j] = p.z;
        s_w[j] = fmaf(r, dual[j], -p.w) - S;
    }
    __syncthreads();

    const int rloc = tid & 31;
    const int cid  = tid >> 5;
    const int rowA = blockIdx.x * RT + rloc;
    const int rowB = rowA + 32;
    const float* xpA = rowP + (size_t)(b * NN + rowA) * 3;
    const float* xpB = rowP + (size_t)(b * NN + rowB) * 3;
    const float ax = xpA[0], ay = xpA[1], az = xpA[2];
    const float bx = xpB[0], by = xpB[1], bz = xpB[2];

    const ull axax = pack2(ax, ax), ayay = pack2(ay, ay), azaz = pack2(az, az);
    const ull bxbx = pack2(bx, bx), byby = pack2(by, by), bzbz = pack2(bz, bz);
    const ull M2   = pack2(12582912.f, 12582912.f);
    const ull NM2  = pack2(-12582912.f, -12582912.f);
    const ull N1_2 = pack2(-1.f, -1.f);
    const ull C3_2 = pack2(0.05592113f, 0.05592113f);
    const ull C2_2 = pack2(0.24263038f, 0.24263038f);
    const ull C1_2 = pack2(0.69312112f, 0.69312112f);
    const ull C0_2 = pack2(0.99992490f, 0.99992490f);

    float aA0 = 0.f, aA1 = 0.f, aB0 = 0.f, aB1 = 0.f;
    ull pA2 = 0ull, pB2 = 0ull;      // packed {0,0}

    const int j0 = cid * 256;
#pragma unroll 2
    for (int j = j0; j < j0 + 256; j += 8) {
        // cols j..j+3 : two MUFU pairs
        ulonglong2 X0 = *(const ulonglong2*)&s_x[j];
        ulonglong2 Y0 = *(const ulonglong2*)&s_y[j];
        ulonglong2 Z0 = *(const ulonglong2*)&s_z[j];
        ulonglong2 W0 = *(const ulonglong2*)&s_w[j];
        {
            ull tA = fma2(axax, X0.x, fma2(ayay, Y0.x, fma2(azaz, Z0.x, W0.x)));
            ull tB = fma2(bxbx, X0.x, fma2(byby, Y0.x, fma2(bzbz, Z0.x, W0.x)));
            float t0, t1, u0, u1;
            unpack2f(tA, t0, t1); unpack2f(tB, u0, u1);
            aA0 += ex2(t0); aA1 += ex2(t1);
            aB0 += ex2(u0); aB1 += ex2(u1);
        }
        {
            ull tA = fma2(axax, X0.y, fma2(ayay, Y0.y, fma2(azaz, Z0.y, W0.y)));
            ull tB = fma2(bxbx, X0.y, fma2(byby, Y0.y, fma2(bzbz, Z0.y, W0.y)));
            float t0, t1, u0, u1;
            unpack2f(tA, t0, t1); unpack2f(tB, u0, u1);
            aA0 += ex2(t0); aA1 += ex2(t1);
            aB0 += ex2(u0); aB1 += ex2(u1);
        }
        // cols j+4..j+7 : one MUFU pair + one poly pair
        ulonglong2 X1 = *(const ulonglong2*)&s_x[j + 4];
        ulonglong2 Y1 = *(const ulonglong2*)&s_y[j + 4];
        ulonglong2 Z1 = *(const ulonglong2*)&s_z[j + 4];
        ulonglong2 W1 = *(const ulonglong2*)&s_w[j + 4];
        {
            ull tA = fma2(axax, X1.x, fma2(ayay, Y1.x, fma2(azaz, Z1.x, W1.x)));
            ull tB = fma2(bxbx, X1.x, fma2(byby, Y1.x, fma2(bzbz, Z1.x, W1.x)));
            float t0, t1, u0, u1;
            unpack2f(tA, t0, t1); unpack2f(tB, u0, u1);
            aA0 += ex2(t0); aA1 += ex2(t1);
            aB0 += ex2(u0); aB1 += ex2(u1);
        }
        {
            ull tA = fma2(axax, X1.y, fma2(ayay, Y1.y, fma2(azaz, Z1.y, W1.y)));
            ull tB = fma2(bxbx, X1.y, fma2(byby, Y1.y, fma2(bzbz, Z1.y, W1.y)));
            pA2 = add2(pA2, pexp2(tA, M2, NM2, N1_2, C3_2, C2_2, C1_2, C0_2));
            pB2 = add2(pB2, pexp2(tB, M2, NM2, N1_2, C3_2, C2_2, C1_2, C0_2));
        }
    }

    float pa0, pa1, pb0, pb1;
    unpack2f(pA2, pa0, pa1);
    unpack2f(pB2, pb0, pb1);
    spart[cid * RT + rloc]      = (aA0 + aA1) + (pa0 + pa1);
    spart[cid * RT + rloc + 32] = (aB0 + aB1) + (pb0 + pb1);
    __syncthreads();

    if (tid < RT) {
        float s = 0.f;
#pragma unroll
        for (int k = 0; k < 8; k++) s += spart[k * RT + tid];
        const int row = blockIdx.x * RT + tid;
        const float* xp = rowP + (size_t)(b * NN + row) * 3;
        float u0 = xp[0], u1 = xp[1], u2 = xp[2];
        const float Bi = -r * (u0 * u0 + u1 * u1 + u2 * u2);
        const float v  = kEPS_LOGMU - kEPS_LN2 * (__log2f(s) + Bi + S);
        // overrelaxation: v_out = old + theta*(v - old); fixed point unchanged
        const float old  = outd[row];
        const float vout = fmaf(kTHETA, v - old, old);
        outd[row] = vout;
        // feed the next launch's shift
        float mv = vout;
#pragma unroll
        for (int o = 16; o; o >>= 1)
            mv = fmaxf(mv, __shfl_xor_sync(0xffffffffu, mv, o));
        if ((tid & 31) == 0) atomicMax(&d_gmax[t + 1][b], fenc(mv));
    }
}

// ---------------------------------------------------------------------------
// Final: sum_{i,j} P_ij * C_ij per block -> d_part  (runs once; R14 config)
// ---------------------------------------------------------------------------
__global__ void __launch_bounds__(256, 4)
final_partial(const float* __restrict__ x, const float* __restrict__ y) {
    __shared__ float4 syc[NN];   // raw y + |y|^2  (32 KB)
    __shared__ float  sg[NN];    // r * g_j        (8 KB)
    __shared__ float  sred[8];

    const int b   = blockIdx.y;
    const int tid = threadIdx.x;
    const float r = kRE;

#pragma unroll
    for (int k = 0; k < NN / 256; k++) {
        int j = k * 256 + tid;
        const float* yp = y + (size_t)(b * NN + j) * 3;
        float y0 = yp[0], y1 = yp[1], y2v = yp[2];
        syc[j] = make_float4(y0, y1, y2v, y0 * y0 + y1 * y1 + y2v * y2v);
        sg[j]  = r * d_g[b * NN + j];
    }
    __syncthreads();

    const int rloc = tid & 31;
    const int cid  = tid >> 5;
    const int rowA = blockIdx.x * RT + rloc;
    const int rowB = rowA + 32;
    const float* xpA = x + (size_t)(b * NN + rowA) * 3;
    const float* xpB = x + (size_t)(b * NN + rowB) * 3;
    const float ax = xpA[0], ay = xpA[1], az = xpA[2];
    const float bx = xpB[0], by = xpB[1], bz = xpB[2];
    const float a2s = ax * ax + ay * ay + az * az;
    const float b2s = bx * bx + by * by + bz * bz;
    const float fa  = r * d_f[b * NN + rowA];
    const float fb  = r * d_f[b * NN + rowB];

    const int j0 = cid * (NN / 8);
    float accA = 0.f, accB = 0.f;
#pragma unroll 4
    for (int j = j0; j < j0 + NN / 8; j++) {
        float4 c  = syc[j];
        float  gj = sg[j];
        float uA = fmaf(ax, c.x, fmaf(ay, c.y, az * c.z));
        float CA = fmaxf(fmaf(-2.f, uA, a2s + c.w), 0.f);
        accA = fmaf(ex2(fmaf(-r, CA, fa + gj)), CA, accA);
        float uB = fmaf(bx, c.x, fmaf(by, c.y, bz * c.z));
        float CB = fmaxf(fmaf(-2.f, uB, b2s + c.w), 0.f);
        accB = fmaf(ex2(fmaf(-r, CB, fb + gj)), CB, accB);
    }

    float acc = accA + accB;
#pragma unroll
    for (int o = 16; o; o >>= 1) acc += __shfl_xor_sync(0xffffffffu, acc, o);
    if ((tid & 31) == 0) sred[tid >> 5] = acc;
    __syncthreads();
    if (tid == 0) {
        float s = ((sred[0] + sred[1]) + (sred[2] + sred[3])) +
                  ((sred[4] + sred[5]) + (sred[6] + sred[7]));
        d_part[blockIdx.y * gridDim.x + blockIdx.x] = s;
    }
}

__global__ void final_reduce(float* __restrict__ out) {
    __shared__ float sr[16];
    int tid = threadIdx.x;             // 512 threads
    float v = d_part[tid];
#pragma unroll
    for (int o = 16; o; o >>= 1) v += __shfl_xor_sync(0xffffffffu, v, o);
    if ((tid & 31) == 0) sr[tid >> 5] = v;
    __syncthreads();
    if (tid == 0) {
        float s = 0.f;
#pragma unroll
        for (int i = 0; i < 16; i++) s += sr[i];
        out[0] = s * (1.f / BB);       // mean = (1/B) * sum P*C
    }
}

// ---------------------------------------------------------------------------
extern "C" void kernel_launch(void* const* d_in, const int* in_sizes, int n_in,
                              void* d_out, int out_size) {
    const float* x = (const float*)d_in[0];
    const float* y = (const float*)d_in[1];

    prep_kernel<<<(BB * NN + 255) / 256, 256>>>(x, y);

    dim3 grid(GRIDX, BB);
    for (int it = 0; it < ITERS; ++it) {
        sink_update<<<grid, 256>>>(x, 0, 2 * it);       // update f from g
        sink_update<<<grid, 256>>>(y, 1, 2 * it + 1);   // update g from f
    }

    dim3 fgrid(GRIDX, BB);
    final_partial<<<fgrid, 256>>>(x, y);
    final_reduce<<<1, GRIDX * BB>>>((float*)d_out);
}